// round 3
// baseline (speedup 1.0000x reference)
#include <cuda_runtime.h>
#include <math.h>

#define NMAX 50000
#define EMAX 500000

// ---------------- static scratch ----------------
__device__ float  g_t [(size_t)256 * EMAX];
__device__ float  g_xn[(size_t)128 * NMAX];
__device__ float  g_si[(size_t)128 * NMAX];
__device__ float  g_sj[(size_t)128 * NMAX];
// transposed (k-major) weights
__device__ float  g_wEa[4 * 128 * 256];   // [l][k][o]  (KE1a+KE1b)
__device__ float  g_wEb[4 * 128 * 256];   // KE1c
__device__ float  g_wNi[4 * 128 * 256];   // 0.5*KN1a + KN1b
__device__ float  g_wNj[4 * 128 * 256];   // 0.5*KN1a - KN1b
__device__ float  g_wNn[4 * 128 * 256];   // KN1c
__device__ float  g_wE2[4 * 256 * 128];   // KE2^T
__device__ float  g_wN2[4 * 256 * 128];   // KN2^T
__device__ float  g_k1n[32 * 128];
__device__ float  g_k2n[128 * 128];
__device__ float  g_k1e[32 * 128];
__device__ float  g_k2e[128 * 128];
__device__ float  g_ko [128 * 128];       // KNout^T zero-padded to 128 rows-out
__device__ double g_acc[20];

// ---------------- f32x2 helpers ----------------
__device__ __forceinline__ unsigned long long dup2(float v) {
    unsigned long long r;
    asm("mov.b64 %0, {%1, %1};" : "=l"(r) : "f"(v));
    return r;
}
__device__ __forceinline__ void ffma2(unsigned long long& d, unsigned long long a, unsigned long long b) {
    asm("fma.rn.f32x2 %0, %1, %2, %0;" : "+l"(d) : "l"(a), "l"(b));
}
__device__ __forceinline__ float2 f2of(unsigned long long u) {
    union { unsigned long long u; float2 f; } cv; cv.u = u; return cv.f;
}

// ---------------- weight prep ----------------
__global__ void prep_kernelA(const float* __restrict__ KE1, const float* __restrict__ KN1,
                             const float* __restrict__ KE2, const float* __restrict__ KN2)
{
    int idx = blockIdx.x * blockDim.x + threadIdx.x;
    if (idx >= 4 * 128 * 256) return;
    int l = idx >> 15;
    int r = idx & 32767;
    {
        int o = r & 255, k = r >> 8;
        size_t src = ((size_t)l * 256 + o) * 384;
        int dst = (l << 15) + k * 256 + o;
        const float* e = KE1 + src;
        const float* n = KN1 + src;
        g_wEa[dst] = e[k] + e[128 + k];
        g_wEb[dst] = e[256 + k];
        float a = n[k], b = n[128 + k];
        g_wNi[dst] = 0.5f * a + b;
        g_wNj[dst] = 0.5f * a - b;
        g_wNn[dst] = n[256 + k];
    }
    {
        int o = r & 127, k = r >> 7;
        int dst = (l << 15) + k * 128 + o;
        g_wE2[dst] = KE2[((size_t)l * 128 + o) * 256 + k];
        g_wN2[dst] = KN2[((size_t)l * 128 + o) * 256 + k];
    }
}

__global__ void prep_kernelB(const float* __restrict__ K1No, const float* __restrict__ K2No,
                             const float* __restrict__ K1Eo, const float* __restrict__ K2Eo,
                             const float* __restrict__ KNout)
{
    int idx = blockIdx.x * blockDim.x + threadIdx.x;
    if (idx >= 128 * 128) return;
    int o = idx & 127, k = idx >> 7;
    if (k < 32) {
        g_k1n[k * 128 + o] = K1No[o * 32 + k];
        g_k1e[k * 128 + o] = K1Eo[o * 32 + k];
    }
    g_k2n[k * 128 + o] = K2No[o * 128 + k];
    g_k2e[k * 128 + o] = K2Eo[o * 128 + k];
    g_ko [k * 128 + o] = (o < 64) ? KNout[o * 128 + k] : 0.f;
}

// ---------------- fused f32x2 GEMM, double-buffered ----------------
__global__ void __launch_bounds__(256, 2)
mm2_kernel(int M, int Oact, int Nn,
           const float* __restrict__ W0, const float* __restrict__ X0, int K0a, int ld0, int ldW0, const int* __restrict__ g0,
           const float* __restrict__ W1, const float* __restrict__ X1, int K1a, int ld1, int ldW1,
           const float* __restrict__ W2, const float* __restrict__ X2, int K2a, int ld2, int ldW2,
           const double* __restrict__ normAcc, double cntInv,
           double* __restrict__ statAcc,
           float* __restrict__ Y, int epi,
           float* __restrict__ si, float* __restrict__ sj,
           const int* __restrict__ iI, const int* __restrict__ jI)
{
    __shared__ __align__(16) float Ws[2][8][132];
    __shared__ __align__(16) float Xs[2][8][132];
    __shared__ int gidx[128], idxI[128], idxJ[128];

    const int tid  = threadIdx.x;
    const int m0   = blockIdx.x * 128;
    const int wb   = blockIdx.y * 128;
    const int lane = tid & 31;
    const int warp = tid >> 5;
    const int wrow = warp >> 2, wcol = warp & 3;
    const int col_t = lane & 3, row_t = lane >> 2;
    const int rbase = wrow * 64 + row_t * 4;
    const int cbase = wcol * 32 + col_t * 4;

    float mean = 0.f, inv = 0.f;
    const bool donorm = (normAcc != nullptr);
    if (donorm) {
        double mu = normAcc[0] * cntInv;
        double va = normAcc[1] * cntInv - mu * mu;
        mean = (float)mu;
        inv  = (float)rsqrt(va + 1e-5);
    }

    if (g0)
        for (int i = tid; i < 128; i += 256) { int m = m0 + i; gidx[i] = (m < M) ? g0[m] : 0; }
    if (epi == 2)
        for (int i = tid; i < 128; i += 256) {
            int m = m0 + i;
            idxI[i] = (m < M) ? iI[m] : 0;
            idxJ[i] = (m < M) ? jI[m] : 0;
        }
    __syncthreads();

    unsigned long long acc[8][4];
    #pragma unroll
    for (int r = 0; r < 8; r++)
        #pragma unroll
        for (int c = 0; c < 4; c++) acc[r][c] = 0ull;

    const int Ks0 = K0a;
    const int Ks1 = W1 ? K1a : 0;
    const int Ks2 = W2 ? K2a : 0;
    const int totT = (Ks0 + Ks1 + Ks2) >> 3;

    float4 wpre, xpre;
    float xg0 = 0.f, xg1 = 0.f, xg2 = 0.f, xg3 = 0.f;

    const int kkS = tid >> 5;
    const int mfS = (tid & 31) * 4;

    // next tile to prefetch
    int pn = 0, kn = 0;
    auto advance = [&]() {
        kn += 8;
        if (pn == 0 && kn >= Ks0) { pn = 1; kn = 0; }
        if (pn == 1 && kn >= Ks1) { pn = 2; kn = 0; }
        if (pn == 2 && kn >= Ks2) { pn = 3; }
    };

    auto prefetch = [&](int p, int k0) {
        const float *W, *X; int ld, ldW; const int* gg = nullptr;
        if (p == 0)      { W = W0; X = X0; ld = ld0; ldW = ldW0; gg = g0; }
        else if (p == 1) { W = W1; X = X1; ld = ld1; ldW = ldW1; }
        else             { W = W2; X = X2; ld = ld2; ldW = ldW2; }
        wpre = *(const float4*)(W + (size_t)(k0 + kkS) * ldW + wb + mfS);
        if (gg) {
            int i0 = tid, i1 = tid + 256, i2 = tid + 512, i3 = tid + 768;
            xg0 = (m0 + (i0 & 127) < M) ? X[(size_t)(k0 + (i0 >> 7)) * ld + gidx[i0 & 127]] : 0.f;
            xg1 = (m0 + (i1 & 127) < M) ? X[(size_t)(k0 + (i1 >> 7)) * ld + gidx[i1 & 127]] : 0.f;
            xg2 = (m0 + (i2 & 127) < M) ? X[(size_t)(k0 + (i2 >> 7)) * ld + gidx[i2 & 127]] : 0.f;
            xg3 = (m0 + (i3 & 127) < M) ? X[(size_t)(k0 + (i3 >> 7)) * ld + gidx[i3 & 127]] : 0.f;
        } else {
            int m = m0 + mfS;
            if (m < M) {
                float4 v = *(const float4*)(X + (size_t)(k0 + kkS) * ld + m);
                if (donorm) {
                    v.x = fmaxf((v.x - mean) * inv, 0.f);
                    v.y = fmaxf((v.y - mean) * inv, 0.f);
                    v.z = fmaxf((v.z - mean) * inv, 0.f);
                    v.w = fmaxf((v.w - mean) * inv, 0.f);
                }
                xpre = v;
            } else xpre = make_float4(0.f, 0.f, 0.f, 0.f);
        }
    };

    auto commit = [&](int buf, bool gath) {
        *(float4*)&Ws[buf][kkS][mfS] = wpre;
        if (gath) {
            Xs[buf][(tid)       >> 7][(tid)       & 127] = xg0;
            Xs[buf][(tid + 256) >> 7][(tid + 256) & 127] = xg1;
            Xs[buf][(tid + 512) >> 7][(tid + 512) & 127] = xg2;
            Xs[buf][(tid + 768) >> 7][(tid + 768) & 127] = xg3;
        } else {
            *(float4*)&Xs[buf][kkS][mfS] = xpre;
        }
    };

    // tile 0: prefetch + commit + sync
    {
        bool gath0 = (g0 != nullptr);
        prefetch(0, 0);
        advance();
        commit(0, gath0);
    }
    __syncthreads();

    for (int tt = 0; tt < totT; tt++) {
        const int cur = tt & 1;
        const bool fetchNext = (tt + 1 < totT);
        bool nGather = false;
        if (fetchNext) {
            nGather = (pn == 0) && (g0 != nullptr);
            prefetch(pn, kn);
            advance();
        }

        // compute 8 k-steps from buffer `cur`
        const float (*Wc)[132] = Ws[cur];
        const float (*Xc)[132] = Xs[cur];
        #pragma unroll
        for (int kk = 0; kk < 8; kk++) {
            float4 wa  = *(const float4*)&Wc[kk][rbase];
            float4 wbv = *(const float4*)&Wc[kk][rbase + 32];
            ulonglong2 xa = *(const ulonglong2*)&Xc[kk][cbase];
            ulonglong2 xb = *(const ulonglong2*)&Xc[kk][cbase + 16];
            unsigned long long d;
            d = dup2(wa.x);  ffma2(acc[0][0], d, xa.x); ffma2(acc[0][1], d, xa.y); ffma2(acc[0][2], d, xb.x); ffma2(acc[0][3], d, xb.y);
            d = dup2(wa.y);  ffma2(acc[1][0], d, xa.x); ffma2(acc[1][1], d, xa.y); ffma2(acc[1][2], d, xb.x); ffma2(acc[1][3], d, xb.y);
            d = dup2(wa.z);  ffma2(acc[2][0], d, xa.x); ffma2(acc[2][1], d, xa.y); ffma2(acc[2][2], d, xb.x); ffma2(acc[2][3], d, xb.y);
            d = dup2(wa.w);  ffma2(acc[3][0], d, xa.x); ffma2(acc[3][1], d, xa.y); ffma2(acc[3][2], d, xb.x); ffma2(acc[3][3], d, xb.y);
            d = dup2(wbv.x); ffma2(acc[4][0], d, xa.x); ffma2(acc[4][1], d, xa.y); ffma2(acc[4][2], d, xb.x); ffma2(acc[4][3], d, xb.y);
            d = dup2(wbv.y); ffma2(acc[5][0], d, xa.x); ffma2(acc[5][1], d, xa.y); ffma2(acc[5][2], d, xb.x); ffma2(acc[5][3], d, xb.y);
            d = dup2(wbv.z); ffma2(acc[6][0], d, xa.x); ffma2(acc[6][1], d, xa.y); ffma2(acc[6][2], d, xb.x); ffma2(acc[6][3], d, xb.y);
            d = dup2(wbv.w); ffma2(acc[7][0], d, xa.x); ffma2(acc[7][1], d, xa.y); ffma2(acc[7][2], d, xb.x); ffma2(acc[7][3], d, xb.y);
        }

        // commit prefetched tile into the other buffer (global loads hidden by compute above)
        if (fetchNext) commit(cur ^ 1, nGather);
        __syncthreads();
    }

    // ----- layernorm stats (producer) -----
    if (statAcc) {
        float s = 0.f, q = 0.f;
        #pragma unroll
        for (int r = 0; r < 8; r++)
            #pragma unroll
            for (int cg = 0; cg < 2; cg++) {
                if (m0 + cbase + cg * 16 < M) {
                    float2 v0 = f2of(acc[r][cg * 2 + 0]);
                    float2 v1 = f2of(acc[r][cg * 2 + 1]);
                    s += v0.x + v0.y + v1.x + v1.y;
                    q += v0.x * v0.x + v0.y * v0.y + v1.x * v1.x + v1.y * v1.y;
                }
            }
        __syncthreads();
        float* redS = (float*)Ws;
        float* redQ = ((float*)Ws) + 256;
        redS[tid] = s; redQ[tid] = q;
        __syncthreads();
        for (int st = 128; st > 0; st >>= 1) {
            if (tid < st) { redS[tid] += redS[tid + st]; redQ[tid] += redQ[tid + st]; }
            __syncthreads();
        }
        if (tid == 0) {
            atomicAdd(statAcc,     (double)redS[0]);
            atomicAdd(statAcc + 1, (double)redQ[0]);
        }
    }

    // ----- epilogue -----
    #pragma unroll
    for (int r = 0; r < 8; r++) {
        int lrow = (r < 4) ? (rbase + r) : (rbase + 32 + r - 4);
        int o = wb + lrow;
        if (o >= Oact) continue;
        #pragma unroll
        for (int cg = 0; cg < 2; cg++) {
            int c = m0 + cbase + cg * 16;
            if (c >= M) continue;
            float2 p0 = f2of(acc[r][cg * 2 + 0]);
            float2 p1 = f2of(acc[r][cg * 2 + 1]);
            size_t off = (size_t)o * M + c;
            if (epi == 0) {
                *(float4*)(Y + off) = make_float4(p0.x, p0.y, p1.x, p1.y);
            } else {
                float4 old = *(float4*)(Y + off);
                old.x += 0.1f * p0.x; old.y += 0.1f * p0.y;
                old.z += 0.1f * p1.x; old.w += 0.1f * p1.y;
                *(float4*)(Y + off) = old;
                if (epi == 2) {
                    int lc = cbase + cg * 16;
                    atomicAdd(si + (size_t)o * Nn + idxI[lc + 0], p0.x);
                    atomicAdd(si + (size_t)o * Nn + idxI[lc + 1], p0.y);
                    atomicAdd(si + (size_t)o * Nn + idxI[lc + 2], p1.x);
                    atomicAdd(si + (size_t)o * Nn + idxI[lc + 3], p1.y);
                    atomicAdd(sj + (size_t)o * Nn + idxJ[lc + 0], p0.x);
                    atomicAdd(sj + (size_t)o * Nn + idxJ[lc + 1], p0.y);
                    atomicAdd(sj + (size_t)o * Nn + idxJ[lc + 2], p1.x);
                    atomicAdd(sj + (size_t)o * Nn + idxJ[lc + 3], p1.y);
                }
            }
        }
    }
}

// ---------------- host-side dispatch ----------------
static inline void mm_launch(int gridy, int M, int Oact,
    const float* W0, const float* X0, int K0, int ld0, int ldW0, const int* g0,
    const float* W1, const float* X1, int K1, int ld1, int ldW1,
    const float* W2, const float* X2, int K2, int ld2, int ldW2,
    const double* nAcc, double cntInv, double* sAcc,
    float* Y, int epi, float* si, float* sj, const int* iI, const int* jI, int Nn)
{
    dim3 grid((M + 127) / 128, gridy);
    mm2_kernel<<<grid, 256>>>(M, Oact, Nn,
        W0, X0, K0, ld0, ldW0, g0,
        W1, X1, K1, ld1, ldW1,
        W2, X2, K2, ld2, ldW2,
        nAcc, cntInv, sAcc, Y, epi, si, sj, iI, jI);
}

extern "C" void kernel_launch(void* const* d_in, const int* in_sizes, int n_in,
                              void* d_out, int out_size)
{
    if (n_in < 13) return;
    const float* xn_in = (const float*)d_in[0];
    const float* xe_in = (const float*)d_in[1];
    const int*   iInd  = (const int*)d_in[2];
    const int*   jInd  = (const int*)d_in[3];
    const float* K1No  = (const float*)d_in[4];
    const float* K2No  = (const float*)d_in[5];
    const float* K1Eo  = (const float*)d_in[6];
    const float* K2Eo  = (const float*)d_in[7];
    const float* KNout = (const float*)d_in[8];
    const float* KE1   = (const float*)d_in[9];
    const float* KE2   = (const float*)d_in[10];
    const float* KN1   = (const float*)d_in[11];
    const float* KN2   = (const float*)d_in[12];

    int N = in_sizes[0] / 32;
    int E = in_sizes[1] / 32;

    float *t, *xn, *si, *sj, *wEa, *wEb, *wNi, *wNj, *wNn, *wE2, *wN2;
    float *k1n, *k2n, *k1e, *k2e, *ko;
    double* acc;
    cudaGetSymbolAddress((void**)&t,   g_t);
    cudaGetSymbolAddress((void**)&xn,  g_xn);
    cudaGetSymbolAddress((void**)&si,  g_si);
    cudaGetSymbolAddress((void**)&sj,  g_sj);
    cudaGetSymbolAddress((void**)&wEa, g_wEa);
    cudaGetSymbolAddress((void**)&wEb, g_wEb);
    cudaGetSymbolAddress((void**)&wNi, g_wNi);
    cudaGetSymbolAddress((void**)&wNj, g_wNj);
    cudaGetSymbolAddress((void**)&wNn, g_wNn);
    cudaGetSymbolAddress((void**)&wE2, g_wE2);
    cudaGetSymbolAddress((void**)&wN2, g_wN2);
    cudaGetSymbolAddress((void**)&k1n, g_k1n);
    cudaGetSymbolAddress((void**)&k2n, g_k2n);
    cudaGetSymbolAddress((void**)&k1e, g_k1e);
    cudaGetSymbolAddress((void**)&k2e, g_k2e);
    cudaGetSymbolAddress((void**)&ko,  g_ko);
    cudaGetSymbolAddress((void**)&acc, g_acc);

    float* out = (float*)d_out;
    float* xe  = out + (size_t)64 * N;

    cudaMemsetAsync(acc, 0, 20 * sizeof(double), 0);
    prep_kernelA<<<(4 * 128 * 256 + 255) / 256, 256>>>(KE1, KN1, KE2, KN2);
    prep_kernelB<<<(128 * 128 + 255) / 256, 256>>>(K1No, K2No, K1Eo, K2Eo, KNout);

    const float* NUL = nullptr;

    // opening node
    mm_launch(1, N, 128, k1n, xn_in, 32, N, 128, nullptr, NUL,0,0,0,0, NUL,0,0,0,0,
              nullptr, 0.0, acc + 0, t, 0, nullptr, nullptr, nullptr, nullptr, 0);
    mm_launch(1, N, 128, k2n, t, 128, N, 128, nullptr, NUL,0,0,0,0, NUL,0,0,0,0,
              acc + 0, 1.0 / (128.0 * N), nullptr, xn, 0, nullptr, nullptr, nullptr, nullptr, 0);

    // opening edge
    mm_launch(1, E, 128, k1e, xe_in, 32, E, 128, nullptr, NUL,0,0,0,0, NUL,0,0,0,0,
              nullptr, 0.0, acc + 2, t, 0, nullptr, nullptr, nullptr, nullptr, 0);
    mm_launch(1, E, 128, k2e, t, 128, E, 128, nullptr, NUL,0,0,0,0, NUL,0,0,0,0,
              acc + 2, 1.0 / (128.0 * E), nullptr, xe, 0, nullptr, nullptr, nullptr, nullptr, 0);

    for (int l = 0; l < 4; l++) {
        double* accE = acc + 4 + 4 * l;
        double* accN = acc + 6 + 4 * l;
        size_t ws = (size_t)l * 32768;

        // edge mm1
        mm_launch(2, E, 256, wEa + ws, xn, 128, N, 256, iInd,
                  wEb + ws, xe, 128, E, 256,
                  NUL, 0, 0, 0, 0,
                  nullptr, 0.0, accE, t, 0, nullptr, nullptr, nullptr, nullptr, 0);

        cudaMemsetAsync(si, 0, (size_t)128 * N * sizeof(float), 0);
        cudaMemsetAsync(sj, 0, (size_t)128 * N * sizeof(float), 0);

        // edge mm2 + scatter
        mm_launch(1, E, 128, wE2 + ws, t, 256, E, 128, nullptr, NUL,0,0,0,0, NUL,0,0,0,0,
                  accE, 1.0 / (256.0 * E), nullptr, xe, 2, si, sj, iInd, jInd, N);

        // node mm1
        mm_launch(2, N, 256, wNi + ws, si, 128, N, 256, nullptr,
                  wNj + ws, sj, 128, N, 256,
                  wNn + ws, xn, 128, N, 256,
                  nullptr, 0.0, accN, t, 0, nullptr, nullptr, nullptr, nullptr, 0);

        // node mm2
        mm_launch(1, N, 128, wN2 + ws, t, 256, N, 128, nullptr, NUL,0,0,0,0, NUL,0,0,0,0,
                  accN, 1.0 / (256.0 * N), nullptr, xn, 1, nullptr, nullptr, nullptr, nullptr, 0);
    }

    // final
    mm_launch(1, N, 64, ko, xn, 128, N, 128, nullptr, NUL,0,0,0,0, NUL,0,0,0,0,
              nullptr, 0.0, nullptr, out, 0, nullptr, nullptr, nullptr, nullptr, 0);
}

// round 4
// speedup vs baseline: 1.0155x; 1.0155x over previous
#include <cuda_runtime.h>
#include <math.h>

#define NMAX 50000
#define EMAX 500000

// ---------------- static scratch ----------------
__device__ float  g_t  [(size_t)256 * EMAX];
__device__ float  g_xn [(size_t)128 * NMAX];
__device__ float  g_xnT[(size_t)128 * NMAX];   // xn transposed: [n][k]
__device__ float  g_si [(size_t)128 * NMAX];
__device__ float  g_sj [(size_t)128 * NMAX];
// k-major weights
__device__ float  g_wEa[4 * 128 * 256];
__device__ float  g_wEb[4 * 128 * 256];
__device__ float  g_wNi[4 * 128 * 256];
__device__ float  g_wNj[4 * 128 * 256];
__device__ float  g_wNn[4 * 128 * 256];
__device__ float  g_wE2[4 * 256 * 128];
__device__ float  g_wN2[4 * 256 * 128];
__device__ float  g_k1n[32 * 128];
__device__ float  g_k2n[128 * 128];
__device__ float  g_k1e[32 * 128];
__device__ float  g_k2e[128 * 128];
__device__ float  g_ko [128 * 128];
__device__ double g_acc[20];

// ---------------- f32x2 helpers ----------------
__device__ __forceinline__ unsigned long long dup2(float v) {
    unsigned long long r;
    asm("mov.b64 %0, {%1, %1};" : "=l"(r) : "f"(v));
    return r;
}
__device__ __forceinline__ void ffma2(unsigned long long& d, unsigned long long a, unsigned long long b) {
    asm("fma.rn.f32x2 %0, %1, %2, %0;" : "+l"(d) : "l"(a), "l"(b));
}
__device__ __forceinline__ float2 f2of(unsigned long long u) {
    union { unsigned long long u; float2 f; } cv; cv.u = u; return cv.f;
}

// ---------------- weight prep ----------------
__global__ void prep_kernelA(const float* __restrict__ KE1, const float* __restrict__ KN1,
                             const float* __restrict__ KE2, const float* __restrict__ KN2)
{
    int idx = blockIdx.x * blockDim.x + threadIdx.x;
    if (idx >= 4 * 128 * 256) return;
    int l = idx >> 15;
    int r = idx & 32767;
    {
        int o = r & 255, k = r >> 8;
        size_t src = ((size_t)l * 256 + o) * 384;
        int dst = (l << 15) + k * 256 + o;
        const float* e = KE1 + src;
        const float* n = KN1 + src;
        g_wEa[dst] = e[k] + e[128 + k];
        g_wEb[dst] = e[256 + k];
        float a = n[k], b = n[128 + k];
        g_wNi[dst] = 0.5f * a + b;
        g_wNj[dst] = 0.5f * a - b;
        g_wNn[dst] = n[256 + k];
    }
    {
        int o = r & 127, k = r >> 7;
        int dst = (l << 15) + k * 128 + o;
        g_wE2[dst] = KE2[((size_t)l * 128 + o) * 256 + k];
        g_wN2[dst] = KN2[((size_t)l * 128 + o) * 256 + k];
    }
}

__global__ void prep_kernelB(const float* __restrict__ K1No, const float* __restrict__ K2No,
                             const float* __restrict__ K1Eo, const float* __restrict__ K2Eo,
                             const float* __restrict__ KNout)
{
    int idx = blockIdx.x * blockDim.x + threadIdx.x;
    if (idx >= 128 * 128) return;
    int o = idx & 127, k = idx >> 7;
    if (k < 32) {
        g_k1n[k * 128 + o] = K1No[o * 32 + k];
        g_k1e[k * 128 + o] = K1Eo[o * 32 + k];
    }
    g_k2n[k * 128 + o] = K2No[o * 128 + k];
    g_k2e[k * 128 + o] = K2Eo[o * 128 + k];
    g_ko [k * 128 + o] = (o < 64) ? KNout[o * 128 + k] : 0.f;
}

// ---------------- xn transpose: [128][N] -> [N][128] ----------------
__global__ void transpose128(const float* __restrict__ src, float* __restrict__ dst, int N)
{
    __shared__ float tile[32][33];
    int nb = blockIdx.x * 32;
    int kb = blockIdx.y * 32;
    int tx = threadIdx.x, ty = threadIdx.y;  // 32 x 8
    #pragma unroll
    for (int i = 0; i < 32; i += 8) {
        int k = kb + ty + i, n = nb + tx;
        tile[ty + i][tx] = (n < N) ? src[(size_t)k * N + n] : 0.f;
    }
    __syncthreads();
    #pragma unroll
    for (int i = 0; i < 32; i += 8) {
        int n = nb + ty + i, k = kb + tx;
        if (n < N) dst[(size_t)n * 128 + k] = tile[tx][ty + i];
    }
}

// ---------------- fused f32x2 GEMM, 3-slot async pipeline ----------------
__global__ void __launch_bounds__(256, 2)
mm3_kernel(int M, int Oact, int Nn,
           const float* __restrict__ W0, const float* __restrict__ X0, int K0, int ld0, int ldW0, const int* __restrict__ g0,
           const float* __restrict__ W1, const float* __restrict__ X1, int K1, int ld1, int ldW1,
           const float* __restrict__ W2, const float* __restrict__ X2, int K2, int ld2, int ldW2,
           const double* __restrict__ normAcc, double cntInv,
           double* __restrict__ statAcc,
           float* __restrict__ Y, int epi,
           float* __restrict__ si, float* __restrict__ sj,
           const int* __restrict__ iI, const int* __restrict__ jI)
{
    __shared__ __align__(16) float Ws[3][8][132];
    __shared__ __align__(16) float Xs[3][8][132];
    __shared__ int gidx[128], idxI[128], idxJ[128];

    const int tid  = threadIdx.x;
    const int m0   = blockIdx.x * 128;
    const int wb   = blockIdx.y * 128;
    const int lane = tid & 31;
    const int warp = tid >> 5;
    const int wrow = warp >> 2, wcol = warp & 3;
    const int col_t = lane & 3, row_t = lane >> 2;
    const int rbase = wrow * 64 + row_t * 4;
    const int cbase = wcol * 32 + col_t * 4;

    const int kkS = tid >> 5;          // staging row (non-gather)
    const int mfS = (tid & 31) * 4;    // staging col group
    const int gC  = tid & 127;         // gather: column
    const int gQ  = tid >> 7;          // gather: k-quad (0/1)

    float mean = 0.f, inv = 0.f;
    const bool donorm = (normAcc != nullptr);
    if (donorm) {
        double mu = normAcc[0] * cntInv;
        double va = normAcc[1] * cntInv - mu * mu;
        mean = (float)mu;
        inv  = (float)rsqrt(va + 1e-5);
    }

    if (g0)
        for (int i = tid; i < 128; i += 256) { int m = m0 + i; gidx[i] = (m < M) ? g0[m] : 0; }
    if (epi == 2)
        for (int i = tid; i < 128; i += 256) {
            int m = m0 + i;
            idxI[i] = (m < M) ? iI[m] : 0;
            idxJ[i] = (m < M) ? jI[m] : 0;
        }
    __syncthreads();

    unsigned long long acc[8][4];
    #pragma unroll
    for (int r = 0; r < 8; r++)
        #pragma unroll
        for (int c = 0; c < 4; c++) acc[r][c] = 0ull;

    const int c0 = K0 >> 3;
    const int c1 = W1 ? (K1 >> 3) : 0;
    const int c2 = W2 ? (K2 >> 3) : 0;
    const int totT = c0 + c1 + c2;

    // per-tile staging: load tile t's W/X fragment into registers
    auto ldgTile = [&](int t, float4& wv, float4& xv, bool& gath) {
        const float *W, *X; int ld, ldW, k0;
        if (t < c0)           { W = W0; X = X0; ld = ld0; ldW = ldW0; k0 = t * 8;            gath = (g0 != nullptr); }
        else if (t < c0 + c1) { W = W1; X = X1; ld = ld1; ldW = ldW1; k0 = (t - c0) * 8;     gath = false; }
        else                  { W = W2; X = X2; ld = ld2; ldW = ldW2; k0 = (t - c0 - c1) * 8; gath = false; }
        wv = *(const float4*)(W + (size_t)(k0 + kkS) * ldW + wb + mfS);
        if (gath) {
            // X is node-major xnT: contiguous 16B per (col, k-quad)
            xv = *(const float4*)(X + (size_t)gidx[gC] * ld + k0 + gQ * 4);
        } else {
            int m = m0 + mfS;
            if (m < M) {
                float4 v = *(const float4*)(X + (size_t)(k0 + kkS) * ld + m);
                if (donorm) {
                    v.x = fmaxf((v.x - mean) * inv, 0.f);
                    v.y = fmaxf((v.y - mean) * inv, 0.f);
                    v.z = fmaxf((v.z - mean) * inv, 0.f);
                    v.w = fmaxf((v.w - mean) * inv, 0.f);
                }
                xv = v;
            } else xv = make_float4(0.f, 0.f, 0.f, 0.f);
        }
    };

    auto stsTile = [&](int slot, const float4& wv, const float4& xv, bool gath) {
        *(float4*)&Ws[slot][kkS][mfS] = wv;
        if (gath) {
            Xs[slot][gQ * 4 + 0][gC] = xv.x;
            Xs[slot][gQ * 4 + 1][gC] = xv.y;
            Xs[slot][gQ * 4 + 2][gC] = xv.z;
            Xs[slot][gQ * 4 + 3][gC] = xv.w;
        } else {
            *(float4*)&Xs[slot][kkS][mfS] = xv;
        }
    };

    // prologue: stage tiles 0 and 1
    {
        float4 wv, xv; bool gf;
        ldgTile(0, wv, xv, gf);
        stsTile(0, wv, xv, gf);
        if (totT > 1) {
            ldgTile(1, wv, xv, gf);
            stsTile(1, wv, xv, gf);
        }
    }

    float4 wpv, xpv; bool gpf = false;
    int slot = 0;

    for (int t = 0; t < totT; t++) {
        __syncthreads();
        const bool more = (t + 2 < totT);
        if (more) ldgTile(t + 2, wpv, xpv, gpf);

        const float (*Wc)[132] = Ws[slot];
        const float (*Xc)[132] = Xs[slot];
        #pragma unroll
        for (int kk = 0; kk < 8; kk++) {
            float4 wa  = *(const float4*)&Wc[kk][rbase];
            float4 wbv = *(const float4*)&Wc[kk][rbase + 32];
            ulonglong2 xa = *(const ulonglong2*)&Xc[kk][cbase];
            ulonglong2 xb = *(const ulonglong2*)&Xc[kk][cbase + 16];
            unsigned long long d;
            d = dup2(wa.x);  ffma2(acc[0][0], d, xa.x); ffma2(acc[0][1], d, xa.y); ffma2(acc[0][2], d, xb.x); ffma2(acc[0][3], d, xb.y);
            d = dup2(wa.y);  ffma2(acc[1][0], d, xa.x); ffma2(acc[1][1], d, xa.y); ffma2(acc[1][2], d, xb.x); ffma2(acc[1][3], d, xb.y);
            d = dup2(wa.z);  ffma2(acc[2][0], d, xa.x); ffma2(acc[2][1], d, xa.y); ffma2(acc[2][2], d, xb.x); ffma2(acc[2][3], d, xb.y);
            d = dup2(wa.w);  ffma2(acc[3][0], d, xa.x); ffma2(acc[3][1], d, xa.y); ffma2(acc[3][2], d, xb.x); ffma2(acc[3][3], d, xb.y);
            d = dup2(wbv.x); ffma2(acc[4][0], d, xa.x); ffma2(acc[4][1], d, xa.y); ffma2(acc[4][2], d, xb.x); ffma2(acc[4][3], d, xb.y);
            d = dup2(wbv.y); ffma2(acc[5][0], d, xa.x); ffma2(acc[5][1], d, xa.y); ffma2(acc[5][2], d, xb.x); ffma2(acc[5][3], d, xb.y);
            d = dup2(wbv.z); ffma2(acc[6][0], d, xa.x); ffma2(acc[6][1], d, xa.y); ffma2(acc[6][2], d, xb.x); ffma2(acc[6][3], d, xb.y);
            d = dup2(wbv.w); ffma2(acc[7][0], d, xa.x); ffma2(acc[7][1], d, xa.y); ffma2(acc[7][2], d, xb.x); ffma2(acc[7][3], d, xb.y);
        }

        if (more) {
            int ds = slot - 1; if (ds < 0) ds = 2;   // (t+2)%3 == (t-1)%3
            stsTile(ds, wpv, xpv, gpf);
        }
        slot++; if (slot == 3) slot = 0;
    }

    // ----- layernorm stats (producer) -----
    if (statAcc) {
        float s = 0.f, q = 0.f;
        #pragma unroll
        for (int r = 0; r < 8; r++)
            #pragma unroll
            for (int cg = 0; cg < 2; cg++) {
                if (m0 + cbase + cg * 16 < M) {
                    float2 v0 = f2of(acc[r][cg * 2 + 0]);
                    float2 v1 = f2of(acc[r][cg * 2 + 1]);
                    s += v0.x + v0.y + v1.x + v1.y;
                    q += v0.x * v0.x + v0.y * v0.y + v1.x * v1.x + v1.y * v1.y;
                }
            }
        __syncthreads();
        float* redS = (float*)Ws;
        float* redQ = ((float*)Ws) + 256;
        redS[tid] = s; redQ[tid] = q;
        __syncthreads();
        for (int st = 128; st > 0; st >>= 1) {
            if (tid < st) { redS[tid] += redS[tid + st]; redQ[tid] += redQ[tid + st]; }
            __syncthreads();
        }
        if (tid == 0) {
            atomicAdd(statAcc,     (double)redS[0]);
            atomicAdd(statAcc + 1, (double)redQ[0]);
        }
    }

    // ----- epilogue -----
    #pragma unroll
    for (int r = 0; r < 8; r++) {
        int lrow = (r < 4) ? (rbase + r) : (rbase + 32 + r - 4);
        int o = wb + lrow;
        if (o >= Oact) continue;
        #pragma unroll
        for (int cg = 0; cg < 2; cg++) {
            int c = m0 + cbase + cg * 16;
            if (c >= M) continue;
            float2 p0 = f2of(acc[r][cg * 2 + 0]);
            float2 p1 = f2of(acc[r][cg * 2 + 1]);
            size_t off = (size_t)o * M + c;
            if (epi == 0) {
                *(float4*)(Y + off) = make_float4(p0.x, p0.y, p1.x, p1.y);
            } else {
                float4 old = *(float4*)(Y + off);
                old.x += 0.1f * p0.x; old.y += 0.1f * p0.y;
                old.z += 0.1f * p1.x; old.w += 0.1f * p1.y;
                *(float4*)(Y + off) = old;
                if (epi == 2) {
                    int lc = cbase + cg * 16;
                    atomicAdd(si + (size_t)o * Nn + idxI[lc + 0], p0.x);
                    atomicAdd(si + (size_t)o * Nn + idxI[lc + 1], p0.y);
                    atomicAdd(si + (size_t)o * Nn + idxI[lc + 2], p1.x);
                    atomicAdd(si + (size_t)o * Nn + idxI[lc + 3], p1.y);
                    atomicAdd(sj + (size_t)o * Nn + idxJ[lc + 0], p0.x);
                    atomicAdd(sj + (size_t)o * Nn + idxJ[lc + 1], p0.y);
                    atomicAdd(sj + (size_t)o * Nn + idxJ[lc + 2], p1.x);
                    atomicAdd(sj + (size_t)o * Nn + idxJ[lc + 3], p1.y);
                }
            }
        }
    }
}

// ---------------- host-side dispatch ----------------
static inline void mm_launch(int gridy, int M, int Oact,
    const float* W0, const float* X0, int K0, int ld0, int ldW0, const int* g0,
    const float* W1, const float* X1, int K1, int ld1, int ldW1,
    const float* W2, const float* X2, int K2, int ld2, int ldW2,
    const double* nAcc, double cntInv, double* sAcc,
    float* Y, int epi, float* si, float* sj, const int* iI, const int* jI, int Nn)
{
    dim3 grid((M + 127) / 128, gridy);
    mm3_kernel<<<grid, 256>>>(M, Oact, Nn,
        W0, X0, K0, ld0, ldW0, g0,
        W1, X1, K1, ld1, ldW1,
        W2, X2, K2, ld2, ldW2,
        nAcc, cntInv, sAcc, Y, epi, si, sj, iI, jI);
}

extern "C" void kernel_launch(void* const* d_in, const int* in_sizes, int n_in,
                              void* d_out, int out_size)
{
    if (n_in < 13) return;
    const float* xn_in = (const float*)d_in[0];
    const float* xe_in = (const float*)d_in[1];
    const int*   iInd  = (const int*)d_in[2];
    const int*   jInd  = (const int*)d_in[3];
    const float* K1No  = (const float*)d_in[4];
    const float* K2No  = (const float*)d_in[5];
    const float* K1Eo  = (const float*)d_in[6];
    const float* K2Eo  = (const float*)d_in[7];
    const float* KNout = (const float*)d_in[8];
    const float* KE1   = (const float*)d_in[9];
    const float* KE2   = (const float*)d_in[10];
    const float* KN1   = (const float*)d_in[11];
    const float* KN2   = (const float*)d_in[12];

    int N = in_sizes[0] / 32;
    int E = in_sizes[1] / 32;

    float *t, *xn, *xnT, *si, *sj, *wEa, *wEb, *wNi, *wNj, *wNn, *wE2, *wN2;
    float *k1n, *k2n, *k1e, *k2e, *ko;
    double* acc;
    cudaGetSymbolAddress((void**)&t,   g_t);
    cudaGetSymbolAddress((void**)&xn,  g_xn);
    cudaGetSymbolAddress((void**)&xnT, g_xnT);
    cudaGetSymbolAddress((void**)&si,  g_si);
    cudaGetSymbolAddress((void**)&sj,  g_sj);
    cudaGetSymbolAddress((void**)&wEa, g_wEa);
    cudaGetSymbolAddress((void**)&wEb, g_wEb);
    cudaGetSymbolAddress((void**)&wNi, g_wNi);
    cudaGetSymbolAddress((void**)&wNj, g_wNj);
    cudaGetSymbolAddress((void**)&wNn, g_wNn);
    cudaGetSymbolAddress((void**)&wE2, g_wE2);
    cudaGetSymbolAddress((void**)&wN2, g_wN2);
    cudaGetSymbolAddress((void**)&k1n, g_k1n);
    cudaGetSymbolAddress((void**)&k2n, g_k2n);
    cudaGetSymbolAddress((void**)&k1e, g_k1e);
    cudaGetSymbolAddress((void**)&k2e, g_k2e);
    cudaGetSymbolAddress((void**)&ko,  g_ko);
    cudaGetSymbolAddress((void**)&acc, g_acc);

    float* out = (float*)d_out;
    float* xe  = out + (size_t)64 * N;

    cudaMemsetAsync(acc, 0, 20 * sizeof(double), 0);
    prep_kernelA<<<(4 * 128 * 256 + 255) / 256, 256>>>(KE1, KN1, KE2, KN2);
    prep_kernelB<<<(128 * 128 + 255) / 256, 256>>>(K1No, K2No, K1Eo, K2Eo, KNout);

    const float* NUL = nullptr;
    dim3 tgrid((N + 31) / 32, 4), tblk(32, 8);

    // opening node
    mm_launch(1, N, 128, k1n, xn_in, 32, N, 128, nullptr, NUL,0,0,0,0, NUL,0,0,0,0,
              nullptr, 0.0, acc + 0, t, 0, nullptr, nullptr, nullptr, nullptr, 0);
    mm_launch(1, N, 128, k2n, t, 128, N, 128, nullptr, NUL,0,0,0,0, NUL,0,0,0,0,
              acc + 0, 1.0 / (128.0 * N), nullptr, xn, 0, nullptr, nullptr, nullptr, nullptr, 0);
    transpose128<<<tgrid, tblk>>>(xn, xnT, N);

    // opening edge
    mm_launch(1, E, 128, k1e, xe_in, 32, E, 128, nullptr, NUL,0,0,0,0, NUL,0,0,0,0,
              nullptr, 0.0, acc + 2, t, 0, nullptr, nullptr, nullptr, nullptr, 0);
    mm_launch(1, E, 128, k2e, t, 128, E, 128, nullptr, NUL,0,0,0,0, NUL,0,0,0,0,
              acc + 2, 1.0 / (128.0 * E), nullptr, xe, 0, nullptr, nullptr, nullptr, nullptr, 0);

    for (int l = 0; l < 4; l++) {
        double* accE = acc + 4 + 4 * l;
        double* accN = acc + 6 + 4 * l;
        size_t ws = (size_t)l * 32768;

        // edge mm1: t[256,E] = wEa @ xnT[iInd]^T + wEb @ xe   (+stats)
        mm_launch(2, E, 256, wEa + ws, xnT, 128, 128, 256, iInd,
                  wEb + ws, xe, 128, E, 256,
                  NUL, 0, 0, 0, 0,
                  nullptr, 0.0, accE, t, 0, nullptr, nullptr, nullptr, nullptr, 0);

        cudaMemsetAsync(si, 0, (size_t)128 * N * sizeof(float), 0);
        cudaMemsetAsync(sj, 0, (size_t)128 * N * sizeof(float), 0);

        // edge mm2 + scatter
        mm_launch(1, E, 128, wE2 + ws, t, 256, E, 128, nullptr, NUL,0,0,0,0, NUL,0,0,0,0,
                  accE, 1.0 / (256.0 * E), nullptr, xe, 2, si, sj, iInd, jInd, N);

        // node mm1
        mm_launch(2, N, 256, wNi + ws, si, 128, N, 256, nullptr,
                  wNj + ws, sj, 128, N, 256,
                  wNn + ws, xn, 128, N, 256,
                  nullptr, 0.0, accN, t, 0, nullptr, nullptr, nullptr, nullptr, 0);

        // node mm2
        mm_launch(1, N, 128, wN2 + ws, t, 256, N, 128, nullptr, NUL,0,0,0,0, NUL,0,0,0,0,
                  accN, 1.0 / (256.0 * N), nullptr, xn, 1, nullptr, nullptr, nullptr, nullptr, 0);
        if (l < 3) transpose128<<<tgrid, tblk>>>(xn, xnT, N);
    }

    // final
    mm_launch(1, N, 64, ko, xn, 128, N, 128, nullptr, NUL,0,0,0,0, NUL,0,0,0,0,
              nullptr, 0.0, nullptr, out, 0, nullptr, nullptr, nullptr, nullptr, 0);
}

// round 5
// speedup vs baseline: 1.1438x; 1.1264x over previous
#include <cuda_runtime.h>
#include <math.h>

#define NMAX 50000
#define EMAX 500000
typedef unsigned long long ull;

// ---------------- static scratch ----------------
__device__ float  g_t  [(size_t)256 * EMAX];
__device__ float  g_xn [(size_t)128 * NMAX];
__device__ float  g_yAT[(size_t)256 * NMAX];   // (wEa @ xn)^T, node-major [n][256]
__device__ float  g_si [(size_t)128 * NMAX];
__device__ float  g_sj [(size_t)128 * NMAX];
// k-major weights
__device__ float  g_wEa[4 * 128 * 256];
__device__ float  g_wEb[4 * 128 * 256];
__device__ float  g_wNi[4 * 128 * 256];
__device__ float  g_wNj[4 * 128 * 256];
__device__ float  g_wNn[4 * 128 * 256];
__device__ float  g_wE2[4 * 256 * 128];
__device__ float  g_wN2[4 * 256 * 128];
__device__ float  g_k1n[32 * 128];
__device__ float  g_k2n[128 * 128];
__device__ float  g_k1e[32 * 128];
__device__ float  g_k2e[128 * 128];
__device__ float  g_ko [128 * 128];
__device__ double g_acc[20];

// ---------------- f32x2 helpers ----------------
__device__ __forceinline__ ull dup2(float v) {
    ull r; asm("mov.b64 %0, {%1, %1};" : "=l"(r) : "f"(v)); return r;
}
__device__ __forceinline__ ull pack2(float lo, float hi) {
    ull r; asm("mov.b64 %0, {%1, %2};" : "=l"(r) : "f"(lo), "f"(hi)); return r;
}
__device__ __forceinline__ void ffma2(ull& d, ull a, ull b) {
    asm("fma.rn.f32x2 %0, %1, %2, %0;" : "+l"(d) : "l"(a), "l"(b));
}
__device__ __forceinline__ float2 f2of(ull u) {
    union { ull u; float2 f; } cv; cv.u = u; return cv.f;
}

// ---------------- weight prep ----------------
__global__ void prep_kernelA(const float* __restrict__ KE1, const float* __restrict__ KN1,
                             const float* __restrict__ KE2, const float* __restrict__ KN2)
{
    int idx = blockIdx.x * blockDim.x + threadIdx.x;
    if (idx >= 4 * 128 * 256) return;
    int l = idx >> 15;
    int r = idx & 32767;
    {
        int o = r & 255, k = r >> 8;
        size_t src = ((size_t)l * 256 + o) * 384;
        int dst = (l << 15) + k * 256 + o;
        const float* e = KE1 + src;
        const float* n = KN1 + src;
        g_wEa[dst] = e[k] + e[128 + k];
        g_wEb[dst] = e[256 + k];
        float a = n[k], b = n[128 + k];
        g_wNi[dst] = 0.5f * a + b;
        g_wNj[dst] = 0.5f * a - b;
        g_wNn[dst] = n[256 + k];
    }
    {
        int o = r & 127, k = r >> 7;
        int dst = (l << 15) + k * 128 + o;
        g_wE2[dst] = KE2[((size_t)l * 128 + o) * 256 + k];
        g_wN2[dst] = KN2[((size_t)l * 128 + o) * 256 + k];
    }
}

__global__ void prep_kernelB(const float* __restrict__ K1No, const float* __restrict__ K2No,
                             const float* __restrict__ K1Eo, const float* __restrict__ K2Eo,
                             const float* __restrict__ KNout)
{
    int idx = blockIdx.x * blockDim.x + threadIdx.x;
    if (idx >= 128 * 128) return;
    int o = idx & 127, k = idx >> 7;
    if (k < 32) {
        g_k1n[k * 128 + o] = K1No[o * 32 + k];
        g_k1e[k * 128 + o] = K1Eo[o * 32 + k];
    }
    g_k2n[k * 128 + o] = K2No[o * 128 + k];
    g_k2e[k * 128 + o] = K2Eo[o * 128 + k];
    g_ko [k * 128 + o] = (o < 64) ? KNout[o * 128 + k] : 0.f;
}

// ---------------- fused f32x2 GEMM ----------------
// acc init from gInit (node-major gather) if given; up to 3 dense K-pairs;
// optional norm+relu on X; optional stats; epi: 0 store, 1 +=0.1, 2 +=0.1+scatter, 3 transposed store.
__global__ void __launch_bounds__(256, 2)
mm4_kernel(int M, int Oact, int Nn,
           const float* __restrict__ W0, const float* __restrict__ X0, int K0, int ld0, int ldW0,
           const float* __restrict__ W1, const float* __restrict__ X1, int K1, int ld1, int ldW1,
           const float* __restrict__ W2, const float* __restrict__ X2, int K2, int ld2, int ldW2,
           const float* __restrict__ gInit, const int* __restrict__ g0,
           const double* __restrict__ normAcc, double cntInv,
           double* __restrict__ statAcc,
           float* __restrict__ Y, int epi,
           float* __restrict__ si, float* __restrict__ sj,
           const int* __restrict__ iI, const int* __restrict__ jI)
{
    __shared__ __align__(16) ull   Wd[2][8][132];
    __shared__ __align__(16) float Xs[2][8][132];
    __shared__ int gidx[128], idxI[128], idxJ[128];

    const int tid  = threadIdx.x;
    const int m0   = blockIdx.x * 128;
    const int wb   = blockIdx.y * 128;
    const int lane = tid & 31;
    const int warp = tid >> 5;
    const int wrow = warp >> 2, wcol = warp & 3;
    const int col_t = lane & 3, row_t = lane >> 2;
    const int rbase = wrow * 64 + row_t * 4;
    const int cbase = wcol * 32 + col_t * 4;

    const int kkS = tid >> 5;
    const int mfS = (tid & 31) * 4;

    float mean = 0.f, inv = 0.f;
    const bool donorm = (normAcc != nullptr);
    if (donorm) {
        double mu = normAcc[0] * cntInv;
        double va = normAcc[1] * cntInv - mu * mu;
        mean = (float)mu;
        inv  = (float)rsqrt(va + 1e-5);
    }

    if (gInit)
        for (int i = tid; i < 128; i += 256) { int m = m0 + i; gidx[i] = (m < M) ? g0[m] : 0; }
    if (epi == 2)
        for (int i = tid; i < 128; i += 256) {
            int m = m0 + i;
            idxI[i] = (m < M) ? iI[m] : 0;
            idxJ[i] = (m < M) ? jI[m] : 0;
        }
    __syncthreads();

    ull acc[8][4];
    if (gInit) {
        #pragma unroll
        for (int j = 0; j < 4; j++) {
            int cA = cbase + (j >> 1) * 16 + (j & 1) * 2;
            int gA = gidx[cA], gB = gidx[cA + 1];
            const float* pA = gInit + (size_t)gA * 256 + wb + rbase;
            const float* pB = gInit + (size_t)gB * 256 + wb + rbase;
            float4 a0 = *(const float4*)(pA);
            float4 a1 = *(const float4*)(pA + 32);
            float4 b0 = *(const float4*)(pB);
            float4 b1 = *(const float4*)(pB + 32);
            acc[0][j] = pack2(a0.x, b0.x);
            acc[1][j] = pack2(a0.y, b0.y);
            acc[2][j] = pack2(a0.z, b0.z);
            acc[3][j] = pack2(a0.w, b0.w);
            acc[4][j] = pack2(a1.x, b1.x);
            acc[5][j] = pack2(a1.y, b1.y);
            acc[6][j] = pack2(a1.z, b1.z);
            acc[7][j] = pack2(a1.w, b1.w);
        }
    } else {
        #pragma unroll
        for (int r = 0; r < 8; r++)
            #pragma unroll
            for (int c = 0; c < 4; c++) acc[r][c] = 0ull;
    }

    const int c0 = K0 >> 3;
    const int c1 = W1 ? (K1 >> 3) : 0;
    const int c2 = W2 ? (K2 >> 3) : 0;
    const int totT = c0 + c1 + c2;

    auto ldgTile = [&](int t, float4& wv, float4& xv) {
        const float *W, *X; int ld, ldW, k0;
        if (t < c0)           { W = W0; X = X0; ld = ld0; ldW = ldW0; k0 = t * 8; }
        else if (t < c0 + c1) { W = W1; X = X1; ld = ld1; ldW = ldW1; k0 = (t - c0) * 8; }
        else                  { W = W2; X = X2; ld = ld2; ldW = ldW2; k0 = (t - c0 - c1) * 8; }
        wv = *(const float4*)(W + (size_t)(k0 + kkS) * ldW + wb + mfS);
        int m = m0 + mfS;
        if (m < M) {
            float4 v = *(const float4*)(X + (size_t)(k0 + kkS) * ld + m);
            if (donorm) {
                v.x = fmaxf((v.x - mean) * inv, 0.f);
                v.y = fmaxf((v.y - mean) * inv, 0.f);
                v.z = fmaxf((v.z - mean) * inv, 0.f);
                v.w = fmaxf((v.w - mean) * inv, 0.f);
            }
            xv = v;
        } else xv = make_float4(0.f, 0.f, 0.f, 0.f);
    };

    auto stsTile = [&](int buf, const float4& wv, const float4& xv) {
        ull* wr = &Wd[buf][kkS][mfS];
        wr[0] = dup2(wv.x); wr[1] = dup2(wv.y); wr[2] = dup2(wv.z); wr[3] = dup2(wv.w);
        *(float4*)&Xs[buf][kkS][mfS] = xv;
    };

    {
        float4 wv, xv;
        ldgTile(0, wv, xv);
        stsTile(0, wv, xv);
    }
    __syncthreads();

    float4 wpv, xpv;
    for (int t = 0; t < totT; t++) {
        const int cur = t & 1;
        const bool more = (t + 1 < totT);
        if (more) ldgTile(t + 1, wpv, xpv);

        #pragma unroll
        for (int kk = 0; kk < 8; kk++) {
            ulonglong2 w01 = *(const ulonglong2*)&Wd[cur][kk][rbase];
            ulonglong2 w23 = *(const ulonglong2*)&Wd[cur][kk][rbase + 2];
            ulonglong2 w45 = *(const ulonglong2*)&Wd[cur][kk][rbase + 32];
            ulonglong2 w67 = *(const ulonglong2*)&Wd[cur][kk][rbase + 34];
            ulonglong2 xa = *(const ulonglong2*)&Xs[cur][kk][cbase];
            ulonglong2 xb = *(const ulonglong2*)&Xs[cur][kk][cbase + 16];
            ffma2(acc[0][0], w01.x, xa.x); ffma2(acc[0][1], w01.x, xa.y); ffma2(acc[0][2], w01.x, xb.x); ffma2(acc[0][3], w01.x, xb.y);
            ffma2(acc[1][0], w01.y, xa.x); ffma2(acc[1][1], w01.y, xa.y); ffma2(acc[1][2], w01.y, xb.x); ffma2(acc[1][3], w01.y, xb.y);
            ffma2(acc[2][0], w23.x, xa.x); ffma2(acc[2][1], w23.x, xa.y); ffma2(acc[2][2], w23.x, xb.x); ffma2(acc[2][3], w23.x, xb.y);
            ffma2(acc[3][0], w23.y, xa.x); ffma2(acc[3][1], w23.y, xa.y); ffma2(acc[3][2], w23.y, xb.x); ffma2(acc[3][3], w23.y, xb.y);
            ffma2(acc[4][0], w45.x, xa.x); ffma2(acc[4][1], w45.x, xa.y); ffma2(acc[4][2], w45.x, xb.x); ffma2(acc[4][3], w45.x, xb.y);
            ffma2(acc[5][0], w45.y, xa.x); ffma2(acc[5][1], w45.y, xa.y); ffma2(acc[5][2], w45.y, xb.x); ffma2(acc[5][3], w45.y, xb.y);
            ffma2(acc[6][0], w67.x, xa.x); ffma2(acc[6][1], w67.x, xa.y); ffma2(acc[6][2], w67.x, xb.x); ffma2(acc[6][3], w67.x, xb.y);
            ffma2(acc[7][0], w67.y, xa.x); ffma2(acc[7][1], w67.y, xa.y); ffma2(acc[7][2], w67.y, xb.x); ffma2(acc[7][3], w67.y, xb.y);
        }

        if (more) stsTile(cur ^ 1, wpv, xpv);
        __syncthreads();
    }

    // ----- layernorm stats (producer) -----
    if (statAcc) {
        float s = 0.f, q = 0.f;
        #pragma unroll
        for (int r = 0; r < 8; r++)
            #pragma unroll
            for (int cg = 0; cg < 2; cg++) {
                if (m0 + cbase + cg * 16 < M) {
                    float2 v0 = f2of(acc[r][cg * 2 + 0]);
                    float2 v1 = f2of(acc[r][cg * 2 + 1]);
                    s += v0.x + v0.y + v1.x + v1.y;
                    q += v0.x * v0.x + v0.y * v0.y + v1.x * v1.x + v1.y * v1.y;
                }
            }
        __syncthreads();
        float* redS = (float*)Wd;
        float* redQ = ((float*)Wd) + 256;
        redS[tid] = s; redQ[tid] = q;
        __syncthreads();
        for (int st = 128; st > 0; st >>= 1) {
            if (tid < st) { redS[tid] += redS[tid + st]; redQ[tid] += redQ[tid + st]; }
            __syncthreads();
        }
        if (tid == 0) {
            atomicAdd(statAcc,     (double)redS[0]);
            atomicAdd(statAcc + 1, (double)redQ[0]);
        }
    }

    // ----- epilogue -----
    if (epi == 3) {
        // transposed store: Y[m][256], rows wb+rbase(+32)
        #pragma unroll
        for (int j = 0; j < 4; j++) {
            #pragma unroll
            for (int h = 0; h < 2; h++) {
                int c = m0 + cbase + (j >> 1) * 16 + (j & 1) * 2 + h;
                if (c >= M) continue;
                float4 v0, v1;
                if (h == 0) {
                    v0 = make_float4(f2of(acc[0][j]).x, f2of(acc[1][j]).x, f2of(acc[2][j]).x, f2of(acc[3][j]).x);
                    v1 = make_float4(f2of(acc[4][j]).x, f2of(acc[5][j]).x, f2of(acc[6][j]).x, f2of(acc[7][j]).x);
                } else {
                    v0 = make_float4(f2of(acc[0][j]).y, f2of(acc[1][j]).y, f2of(acc[2][j]).y, f2of(acc[3][j]).y);
                    v1 = make_float4(f2of(acc[4][j]).y, f2of(acc[5][j]).y, f2of(acc[6][j]).y, f2of(acc[7][j]).y);
                }
                float* dst = Y + (size_t)c * 256 + wb + rbase;
                *(float4*)(dst)      = v0;
                *(float4*)(dst + 32) = v1;
            }
        }
        return;
    }

    #pragma unroll
    for (int r = 0; r < 8; r++) {
        int lrow = (r < 4) ? (rbase + r) : (rbase + 32 + r - 4);
        int o = wb + lrow;
        if (o >= Oact) continue;
        #pragma unroll
        for (int cg = 0; cg < 2; cg++) {
            int c = m0 + cbase + cg * 16;
            if (c >= M) continue;
            float2 p0 = f2of(acc[r][cg * 2 + 0]);
            float2 p1 = f2of(acc[r][cg * 2 + 1]);
            size_t off = (size_t)o * M + c;
            if (epi == 0) {
                *(float4*)(Y + off) = make_float4(p0.x, p0.y, p1.x, p1.y);
            } else {
                float4 old = *(float4*)(Y + off);
                old.x += 0.1f * p0.x; old.y += 0.1f * p0.y;
                old.z += 0.1f * p1.x; old.w += 0.1f * p1.y;
                *(float4*)(Y + off) = old;
                if (epi == 2) {
                    int lc = cbase + cg * 16;
                    atomicAdd(si + (size_t)o * Nn + idxI[lc + 0], p0.x);
                    atomicAdd(si + (size_t)o * Nn + idxI[lc + 1], p0.y);
                    atomicAdd(si + (size_t)o * Nn + idxI[lc + 2], p1.x);
                    atomicAdd(si + (size_t)o * Nn + idxI[lc + 3], p1.y);
                    atomicAdd(sj + (size_t)o * Nn + idxJ[lc + 0], p0.x);
                    atomicAdd(sj + (size_t)o * Nn + idxJ[lc + 1], p0.y);
                    atomicAdd(sj + (size_t)o * Nn + idxJ[lc + 2], p1.x);
                    atomicAdd(sj + (size_t)o * Nn + idxJ[lc + 3], p1.y);
                }
            }
        }
    }
}

// ---------------- host-side dispatch ----------------
static inline void mm_launch(int gridy, int M, int Oact,
    const float* W0, const float* X0, int K0, int ld0, int ldW0,
    const float* W1, const float* X1, int K1, int ld1, int ldW1,
    const float* W2, const float* X2, int K2, int ld2, int ldW2,
    const float* gInit, const int* g0,
    const double* nAcc, double cntInv, double* sAcc,
    float* Y, int epi, float* si, float* sj, const int* iI, const int* jI, int Nn)
{
    dim3 grid((M + 127) / 128, gridy);
    mm4_kernel<<<grid, 256>>>(M, Oact, Nn,
        W0, X0, K0, ld0, ldW0,
        W1, X1, K1, ld1, ldW1,
        W2, X2, K2, ld2, ldW2,
        gInit, g0,
        nAcc, cntInv, sAcc, Y, epi, si, sj, iI, jI);
}

extern "C" void kernel_launch(void* const* d_in, const int* in_sizes, int n_in,
                              void* d_out, int out_size)
{
    if (n_in < 13) return;
    const float* xn_in = (const float*)d_in[0];
    const float* xe_in = (const float*)d_in[1];
    const int*   iInd  = (const int*)d_in[2];
    const int*   jInd  = (const int*)d_in[3];
    const float* K1No  = (const float*)d_in[4];
    const float* K2No  = (const float*)d_in[5];
    const float* K1Eo  = (const float*)d_in[6];
    const float* K2Eo  = (const float*)d_in[7];
    const float* KNout = (const float*)d_in[8];
    const float* KE1   = (const float*)d_in[9];
    const float* KE2   = (const float*)d_in[10];
    const float* KN1   = (const float*)d_in[11];
    const float* KN2   = (const float*)d_in[12];

    int N = in_sizes[0] / 32;
    int E = in_sizes[1] / 32;

    float *t, *xn, *yAT, *si, *sj, *wEa, *wEb, *wNi, *wNj, *wNn, *wE2, *wN2;
    float *k1n, *k2n, *k1e, *k2e, *ko;
    double* acc;
    cudaGetSymbolAddress((void**)&t,   g_t);
    cudaGetSymbolAddress((void**)&xn,  g_xn);
    cudaGetSymbolAddress((void**)&yAT, g_yAT);
    cudaGetSymbolAddress((void**)&si,  g_si);
    cudaGetSymbolAddress((void**)&sj,  g_sj);
    cudaGetSymbolAddress((void**)&wEa, g_wEa);
    cudaGetSymbolAddress((void**)&wEb, g_wEb);
    cudaGetSymbolAddress((void**)&wNi, g_wNi);
    cudaGetSymbolAddress((void**)&wNj, g_wNj);
    cudaGetSymbolAddress((void**)&wNn, g_wNn);
    cudaGetSymbolAddress((void**)&wE2, g_wE2);
    cudaGetSymbolAddress((void**)&wN2, g_wN2);
    cudaGetSymbolAddress((void**)&k1n, g_k1n);
    cudaGetSymbolAddress((void**)&k2n, g_k2n);
    cudaGetSymbolAddress((void**)&k1e, g_k1e);
    cudaGetSymbolAddress((void**)&k2e, g_k2e);
    cudaGetSymbolAddress((void**)&ko,  g_ko);
    cudaGetSymbolAddress((void**)&acc, g_acc);

    float* out = (float*)d_out;
    float* xe  = out + (size_t)64 * N;

    cudaMemsetAsync(acc, 0, 20 * sizeof(double), 0);
    prep_kernelA<<<(4 * 128 * 256 + 255) / 256, 256>>>(KE1, KN1, KE2, KN2);
    prep_kernelB<<<(128 * 128 + 255) / 256, 256>>>(K1No, K2No, K1Eo, K2Eo, KNout);

    const float* NUL = nullptr;
    const int*   NIL = nullptr;

    // opening node
    mm_launch(1, N, 128, k1n, xn_in, 32, N, 128, NUL,0,0,0,0, NUL,0,0,0,0, NUL, NIL,
              nullptr, 0.0, acc + 0, t, 0, nullptr, nullptr, nullptr, nullptr, 0);
    mm_launch(1, N, 128, k2n, t, 128, N, 128, NUL,0,0,0,0, NUL,0,0,0,0, NUL, NIL,
              acc + 0, 1.0 / (128.0 * N), nullptr, xn, 0, nullptr, nullptr, nullptr, nullptr, 0);

    // opening edge
    mm_launch(1, E, 128, k1e, xe_in, 32, E, 128, NUL,0,0,0,0, NUL,0,0,0,0, NUL, NIL,
              nullptr, 0.0, acc + 2, t, 0, nullptr, nullptr, nullptr, nullptr, 0);
    mm_launch(1, E, 128, k2e, t, 128, E, 128, NUL,0,0,0,0, NUL,0,0,0,0, NUL, NIL,
              acc + 2, 1.0 / (128.0 * E), nullptr, xe, 0, nullptr, nullptr, nullptr, nullptr, 0);

    for (int l = 0; l < 4; l++) {
        double* accE = acc + 4 + 4 * l;
        double* accN = acc + 6 + 4 * l;
        size_t ws = (size_t)l * 32768;

        // yAT = (wEa @ xn)^T, node-major [n][256]
        mm_launch(2, N, 256, wEa + ws, xn, 128, N, 256, NUL,0,0,0,0, NUL,0,0,0,0, NUL, NIL,
                  nullptr, 0.0, nullptr, yAT, 3, nullptr, nullptr, nullptr, nullptr, 0);

        // edge mm1': t[256,E] = gather(yAT, iInd) + wEb @ xe   (+stats)
        mm_launch(2, E, 256, wEb + ws, xe, 128, E, 256, NUL,0,0,0,0, NUL,0,0,0,0, yAT, iInd,
                  nullptr, 0.0, accE, t, 0, nullptr, nullptr, nullptr, nullptr, 0);

        cudaMemsetAsync(si, 0, (size_t)128 * N * sizeof(float), 0);
        cudaMemsetAsync(sj, 0, (size_t)128 * N * sizeof(float), 0);

        // edge mm2: xec = KE2 @ relu(norm(t)); xe += 0.1*xec; scatter -> si,sj
        mm_launch(1, E, 128, wE2 + ws, t, 256, E, 128, NUL,0,0,0,0, NUL,0,0,0,0, NUL, NIL,
                  accE, 1.0 / (256.0 * E), nullptr, xe, 2, si, sj, iInd, jInd, N);

        // node mm1: u[256,N] = Wi@si + Wj@sj + Wn@xn   (+stats)
        mm_launch(2, N, 256, wNi + ws, si, 128, N, 256,
                  wNj + ws, sj, 128, N, 256,
                  wNn + ws, xn, 128, N, 256, NUL, NIL,
                  nullptr, 0.0, accN, t, 0, nullptr, nullptr, nullptr, nullptr, 0);

        // node mm2: xn += 0.1 * (KN2 @ relu(norm(u)))
        mm_launch(1, N, 128, wN2 + ws, t, 256, N, 128, NUL,0,0,0,0, NUL,0,0,0,0, NUL, NIL,
                  accN, 1.0 / (256.0 * N), nullptr, xn, 1, nullptr, nullptr, nullptr, nullptr, 0);
    }

    // final: out[64,N] = KNout @ xn
    mm_launch(1, N, 64, ko, xn, 128, N, 128, NUL,0,0,0,0, NUL,0,0,0,0, NUL, NIL,
              nullptr, 0.0, nullptr, out, 0, nullptr, nullptr, nullptr, nullptr, 0);
}